// round 14
// baseline (speedup 1.0000x reference)
#include <cuda_runtime.h>
#include <math.h>
#include <stdint.h>

typedef unsigned long long u64;

#define GMAX 10240
#define PMAX (GMAX / 2)
#define BMAX 32768
#define NW 8
#define BLOCK 256
#define RPB 64
#define SPLIT 5

// g-pair packed tables (no duplication):
// T1 (pass 1): v[0..8] = {Yi[g0], Yi[g1]} pairs, v[9] = pad      -> 80 B
// T2 (pass 2): v[0..8] = Y pairs, v[9]=gx pair, v[10]=gy, v[11]=gz -> 96 B
struct __align__(16) T1e { u64 v[10]; };
struct __align__(16) T2e { u64 v[12]; };
__device__ T1e g_T1[PMAX];
__device__ T2e g_T2[PMAX];

// cross-block reduction scratch: packed (sortable_value<<32 | ~index)
__device__ u64 g_part1[BMAX];
__device__ u64 g_part2[BMAX];

// packed(-inf, idx=0): key(-inf)=0x007FFFFF, ~0 = 0xFFFFFFFF
#define INIT_CAND 0x007FFFFFFFFFFFFFULL

__device__ __forceinline__ u64 packcand(float v, int idx) {
    unsigned b = __float_as_uint(v);
    unsigned key = (b & 0x80000000u) ? ~b : (b | 0x80000000u);
    return ((u64)key << 32) | (unsigned)(~idx);
}

__device__ __forceinline__ u64 dup2(float f) {
    u64 r; asm("mov.b64 %0, {%1, %1};" : "=l"(r) : "f"(f)); return r;
}
__device__ __forceinline__ u64 pk2(float lo, float hi) {
    u64 r; asm("mov.b64 %0, {%1, %2};" : "=l"(r) : "f"(lo), "f"(hi)); return r;
}
__device__ __forceinline__ void upk2(u64 v, float& lo, float& hi) {
    asm("mov.b64 {%0, %1}, %2;" : "=f"(lo), "=f"(hi) : "l"(v));
}
__device__ __forceinline__ u64 fma2(u64 a, u64 b, u64 c) {
    u64 r; asm("fma.rn.f32x2 %0, %1, %2, %3;" : "=l"(r) : "l"(a), "l"(b), "l"(c)); return r;
}
__device__ __forceinline__ u64 mul2(u64 a, u64 b) {
    u64 r; asm("mul.rn.f32x2 %0, %1, %2;" : "=l"(r) : "l"(a), "l"(b)); return r;
}

// 9-term SH dot, SINGLE sequential chain per f32x2 half — exact R1 rounding
// order (verified rel_err 4.8e-8). DO NOT re-associate.
__device__ __forceinline__ u64 sig9p(const u64* C, ulonglong2 q0, ulonglong2 q1,
                                     ulonglong2 q2, ulonglong2 q3, u64 y8) {
    u64 acc = mul2(C[0], q0.x);
    acc = fma2(C[1], q0.y, acc);
    acc = fma2(C[2], q1.x, acc);
    acc = fma2(C[3], q1.y, acc);
    acc = fma2(C[4], q2.x, acc);
    acc = fma2(C[5], q2.y, acc);
    acc = fma2(C[6], q3.x, acc);
    acc = fma2(C[7], q3.y, acc);
    acc = fma2(C[8], y8, acc);
    return acc;
}
__device__ __forceinline__ u64 dot3p(u64 zx, u64 zy, u64 zz, u64 gx, u64 gy, u64 gz) {
    u64 d = mul2(zx, gx);
    d = fma2(zy, gy, d);
    return fma2(zz, gz, d);
}
// lower-g half checked first -> first-index tie-break preserved (strict >)
__device__ __forceinline__ void amax2(u64 s, int g0, float& bv, int& bi) {
    float lo, hi; upk2(s, lo, hi);
    if (lo > bv) { bv = lo; bi = g0; }
    if (hi > bv) { bv = hi; bi = g0 + 1; }
}
__device__ __forceinline__ void amaxm2(u64 s, u64 d, int g0, float& bv, int& bi) {
    float lo, hi, dl, dh; upk2(s, lo, hi); upk2(d, dl, dh);
    if (fabsf(dl) < 0.2f && lo > bv) { bv = lo; bi = g0; }
    if (fabsf(dh) < 0.2f && hi > bv) { bv = hi; bi = g0 + 1; }
}

__device__ __forceinline__ void shY(const float* __restrict__ grid, int g,
                                    float* Y, float* gv) {
    float gx = grid[3 * g + 0], gy = grid[3 * g + 1], gz = grid[3 * g + 2];
    gv[0] = gx; gv[1] = gy; gv[2] = gz;
    float n = sqrtf(gx * gx + gy * gy + gz * gz);
    float inv = 1.0f / fmaxf(n, 1e-12f);
    float x = gx * inv, y = gy * inv, z = gz * inv;
    float x2 = x * x, y2 = y * y, z2 = z * z;
    Y[0] = 2.5033429417967046f * (x * y * (x2 - y2));
    Y[1] = 1.7701307697799304f * (y * z * (3.0f * x2 - y2));
    Y[2] = 0.9461746957575601f * (x * y * (7.0f * z2 - 1.0f));
    Y[3] = 0.6690465435572892f * (y * z * (7.0f * z2 - 3.0f));
    Y[4] = 0.10578554691520431f * (35.0f * z2 * z2 - 30.0f * z2 + 3.0f);
    Y[5] = 0.6690465435572892f * (x * z * (7.0f * z2 - 3.0f));
    Y[6] = 0.47308734787878004f * ((x2 - y2) * (7.0f * z2 - 1.0f));
    Y[7] = 1.7701307697799304f * (x * z * (x2 - y2));
    Y[8] = 0.6258357354491761f * (x2 * x2 - 6.0f * x2 * y2 + y2 * y2);
}

// precompute SH table; also initializes per-row reduction scratch (fused).
__global__ void sh_precompute(const float* __restrict__ grid, int G, int P, int B) {
    int i = blockIdx.x * blockDim.x + threadIdx.x;
    if (i < B) { g_part1[i] = INIT_CAND; g_part2[i] = INIT_CAND; }
    if (i >= P) return;
    int g0 = 2 * i;
    int g1 = min(2 * i + 1, G - 1);
    float Ya[9], Yb[9], ga[3], gb[3];
    shY(grid, g0, Ya, ga);
    shY(grid, g1, Yb, gb);
    T1e t1; T2e t2;
#pragma unroll
    for (int q = 0; q < 9; q++) {
        u64 pr = pk2(Ya[q], Yb[q]);
        t1.v[q] = pr; t2.v[q] = pr;
    }
    t1.v[9] = 0;
    t2.v[9]  = pk2(ga[0], gb[0]);
    t2.v[10] = pk2(ga[1], gb[1]);
    t2.v[11] = pk2(ga[2], gb[2]);
    g_T1[i] = t1;
    g_T2[i] = t2;
}

// ---------------------------------------------------------------------------
// Pass 1: direct LDG from the L2-resident table (no smem staging, no chunk
// barriers). 1280 blocks; warps free-run over interleaved pair indices; all
// lanes of a warp broadcast-read the same entry (one sector per load).
// ---------------------------------------------------------------------------
__global__ __launch_bounds__(BLOCK, 3) void pass1_kernel(
    const float* __restrict__ f4, int B, int P, int Pq)
{
    __shared__ float s_pv[NW][RPB];
    __shared__ int s_pidx[NW][RPB];

    const int tid = threadIdx.x;
    const int lane = tid & 31;
    const int wid = tid >> 5;
    const int rowbase = blockIdx.x * RPB;
    const int p0 = blockIdx.y * Pq;
    const int pend = min(P, p0 + Pq);
    const float NEG_INF = __int_as_float(0xff800000);

    const int rA = rowbase + lane;
    const int rB = rA + 32;

    u64 FA[9], FB[9];
#pragma unroll
    for (int i = 0; i < 9; i++) {
        FA[i] = dup2((rA < B) ? f4[rA * 9 + i] : 0.0f);
        FB[i] = dup2((rB < B) ? f4[rB * 9 + i] : 0.0f);
    }

    float bvA = NEG_INF, bvB = NEG_INF;
    int biA = 0, biB = 0;

    const T1e* __restrict__ T1 = g_T1;
    for (int k = p0 + wid; k < pend; k += NW) {
        const ulonglong2* e = (const ulonglong2*)&T1[k];
        ulonglong2 q0 = e[0], q1 = e[1], q2 = e[2], q3 = e[3], q4 = e[4];
        u64 aA = sig9p(FA, q0, q1, q2, q3, q4.x);
        u64 aB = sig9p(FB, q0, q1, q2, q3, q4.x);
        int g0 = 2 * k;
        amax2(aA, g0, bvA, biA);
        amax2(aB, g0, bvB, biB);
    }

    s_pv[wid][lane] = bvA;      s_pidx[wid][lane] = biA;
    s_pv[wid][lane + 32] = bvB; s_pidx[wid][lane + 32] = biB;
    __syncthreads();
    if (tid < RPB) {
        int row = rowbase + tid;
        if (row < B) {
            float v = s_pv[0][tid]; int idx = s_pidx[0][tid];
#pragma unroll
            for (int w = 1; w < NW; w++) {
                float ov = s_pv[w][tid]; int oi = s_pidx[w][tid];
                if (ov > v || (ov == v && oi < idx)) { v = ov; idx = oi; }
            }
            atomicMax((unsigned long long*)&g_part1[row], packcand(v, idx));
        }
    }
}

// ---------------------------------------------------------------------------
// Pass 2: masked argmax, direct LDG; z axis read inline from g_part1.
// ---------------------------------------------------------------------------
__global__ __launch_bounds__(BLOCK, 3) void pass2_kernel(
    const float* __restrict__ f4, const float* __restrict__ grid,
    int B, int P, int Pq)
{
    __shared__ float s_pv[NW][RPB];
    __shared__ int s_pidx[NW][RPB];

    const int tid = threadIdx.x;
    const int lane = tid & 31;
    const int wid = tid >> 5;
    const int rowbase = blockIdx.x * RPB;
    const int p0 = blockIdx.y * Pq;
    const int pend = min(P, p0 + Pq);
    const float NEG_INF = __int_as_float(0xff800000);

    const int rA = rowbase + lane;
    const int rB = rA + 32;

    u64 FA[9], FB[9];
#pragma unroll
    for (int i = 0; i < 9; i++) {
        FA[i] = dup2((rA < B) ? f4[rA * 9 + i] : 0.0f);
        FB[i] = dup2((rB < B) ? f4[rB * 9 + i] : 0.0f);
    }
    int izA = (rA < B) ? ~(unsigned)g_part1[rA] : 0;
    int izB = (rB < B) ? ~(unsigned)g_part1[rB] : 0;
    const u64 ZAx = dup2(grid[3 * izA + 0]), ZAy = dup2(grid[3 * izA + 1]), ZAz = dup2(grid[3 * izA + 2]);
    const u64 ZBx = dup2(grid[3 * izB + 0]), ZBy = dup2(grid[3 * izB + 1]), ZBz = dup2(grid[3 * izB + 2]);

    float bvA = NEG_INF, bvB = NEG_INF;
    int biA = 0, biB = 0;

    const T2e* __restrict__ T2 = g_T2;
    for (int k = p0 + wid; k < pend; k += NW) {
        const ulonglong2* e = (const ulonglong2*)&T2[k];
        ulonglong2 q0 = e[0], q1 = e[1], q2 = e[2], q3 = e[3], q4 = e[4], q5 = e[5];
        u64 aA = sig9p(FA, q0, q1, q2, q3, q4.x);
        u64 aB = sig9p(FB, q0, q1, q2, q3, q4.x);
        u64 dA = dot3p(ZAx, ZAy, ZAz, q4.y, q5.x, q5.y);
        u64 dB = dot3p(ZBx, ZBy, ZBz, q4.y, q5.x, q5.y);
        int g0 = 2 * k;
        amaxm2(aA, dA, g0, bvA, biA);
        amaxm2(aB, dB, g0, bvB, biB);
    }

    s_pv[wid][lane] = bvA;      s_pidx[wid][lane] = biA;
    s_pv[wid][lane + 32] = bvB; s_pidx[wid][lane + 32] = biB;
    __syncthreads();
    if (tid < RPB) {
        int row = rowbase + tid;
        if (row < B) {
            float v = s_pv[0][tid]; int idx = s_pidx[0][tid];
#pragma unroll
            for (int w = 1; w < NW; w++) {
                float ov = s_pv[w][tid]; int oi = s_pidx[w][tid];
                if (ov > v || (ov == v && oi < idx)) { v = ov; idx = oi; }
            }
            atomicMax((unsigned long long*)&g_part2[row], packcand(v, idx));
        }
    }
}

// ---------------------------------------------------------------------------
// Epilogue: Gram-Schmidt + matrix->quaternion + boundary map.
// ---------------------------------------------------------------------------
__global__ void epilogue_kernel(const float* __restrict__ f0,
                                const float* __restrict__ grid,
                                float* __restrict__ out, int B)
{
    int row = blockIdx.x * blockDim.x + threadIdx.x;
    if (row >= B) return;
    int zi = ~(unsigned)g_part1[row];
    int xi = ~(unsigned)g_part2[row];
    float xr0 = grid[3 * xi + 0], xr1 = grid[3 * xi + 1], xr2 = grid[3 * xi + 2];
    float zr0 = grid[3 * zi + 0], zr1 = grid[3 * zi + 1], zr2 = grid[3 * zi + 2];
    float zn = sqrtf(zr0 * zr0 + zr1 * zr1 + zr2 * zr2);
    float zinv = 1.0f / fmaxf(zn, 1e-12f);
    float z0 = zr0 * zinv, z1 = zr1 * zinv, z2 = zr2 * zinv;
    float pr = xr0 * z0 + xr1 * z1 + xr2 * z2;
    float x0 = xr0 - pr * z0, x1 = xr1 - pr * z1, x2 = xr2 - pr * z2;
    float xn = sqrtf(x0 * x0 + x1 * x1 + x2 * x2);
    float xinv = 1.0f / fmaxf(xn, 1e-12f);
    x0 *= xinv; x1 *= xinv; x2 *= xinv;
    float y0 = z1 * x2 - z2 * x1;
    float y1 = z2 * x0 - z0 * x2;
    float y2 = z0 * x1 - z1 * x0;
    float m00 = x0, m01 = y0, m02 = z0;
    float m10 = x1, m11 = y1, m12 = z1;
    float m20 = x2, m21 = y2, m22 = z2;
    float qa0 = sqrtf(fmaxf(1.0f + m00 + m11 + m22, 0.0f));
    float qa1 = sqrtf(fmaxf(1.0f + m00 - m11 - m22, 0.0f));
    float qa2 = sqrtf(fmaxf(1.0f - m00 + m11 - m22, 0.0f));
    float qa3 = sqrtf(fmaxf(1.0f - m00 - m11 + m22, 0.0f));
    float c0[4] = {qa0 * qa0, m21 - m12, m02 - m20, m10 - m01};
    float c1[4] = {m21 - m12, qa1 * qa1, m10 + m01, m02 + m20};
    float c2[4] = {m02 - m20, m10 + m01, qa2 * qa2, m12 + m21};
    float c3[4] = {m10 - m01, m20 + m02, m21 + m12, qa3 * qa3};
    int best = 0; float bq = qa0;
    if (qa1 > bq) { bq = qa1; best = 1; }
    if (qa2 > bq) { bq = qa2; best = 2; }
    if (qa3 > bq) { bq = qa3; best = 3; }
    const float* cr = (best == 0) ? c0 : (best == 1) ? c1 : (best == 2) ? c2 : c3;
    float dn = 2.0f * fmaxf(bq, 0.1f);
    out[row * 4 + 0] = cr[0] / dn;
    out[row * 4 + 1] = cr[1] / dn;
    out[row * 4 + 2] = cr[2] / dn;
    out[row * 4 + 3] = cr[3] / dn;
    out[4 * B + row] = f0[row] * 57.29577951308232f;
}

extern "C" void kernel_launch(void* const* d_in, const int* in_sizes, int n_in,
                              void* d_out, int out_size) {
    const float* f0 = (const float*)d_in[0];
    const float* f4 = (const float*)d_in[2];
    const float* grid = (const float*)d_in[4];
    int B = in_sizes[0];
    int G = in_sizes[4] / 3;
    if (G > GMAX) G = GMAX;
    if (B > BMAX) B = BMAX;
    int P = (G + 1) / 2;
    int Pq = (P + SPLIT - 1) / SPLIT;

    int pre_n = (P > B) ? P : B;
    sh_precompute<<<(pre_n + 255) / 256, 256>>>(grid, G, P, B);

    dim3 gsplit((B + RPB - 1) / RPB, SPLIT);
    pass1_kernel<<<gsplit, BLOCK>>>(f4, B, P, Pq);
    pass2_kernel<<<gsplit, BLOCK>>>(f4, grid, B, P, Pq);
    epilogue_kernel<<<(B + 255) / 256, 256>>>(f0, grid, (float*)d_out, B);
}

// round 15
// speedup vs baseline: 1.2327x; 1.2327x over previous
#include <cuda_runtime.h>
#include <math.h>
#include <stdint.h>

typedef unsigned long long u64;

#define GMAX 10240
#define PMAX (GMAX / 2)
#define BMAX 32768
#define NW 8
#define BLOCK 256
#define RPB1 128   // pass1: 4 rows per lane
#define RPB2 64    // pass2: 2 rows per lane (R8 config)
#define CHP 192    // pass1 chunk pairs (2*192*80 = 30.7KB)
#define CHP2 160   // pass2 chunk pairs (2*160*96 = 30.7KB)
#define SPLIT1 9
#define SPLIT2 5

// g-pair packed tables (no duplication):
// T1 (pass 1): v[0..8] = {Yi[g0], Yi[g1]} pairs, v[9] = pad      -> 80 B
// T2 (pass 2): v[0..8] = Y pairs, v[9]=gx pair, v[10]=gy, v[11]=gz -> 96 B
struct __align__(16) T1e { u64 v[10]; };
struct __align__(16) T2e { u64 v[12]; };
__device__ T1e g_T1[PMAX];
__device__ T2e g_T2[PMAX];

// cross-block reduction scratch: packed (sortable_value<<32 | ~index)
__device__ u64 g_part1[BMAX];
__device__ u64 g_part2[BMAX];

// packed(-inf, idx=0): key(-inf)=0x007FFFFF, ~0 = 0xFFFFFFFF
#define INIT_CAND 0x007FFFFFFFFFFFFFULL

__device__ __forceinline__ u64 packcand(float v, int idx) {
    unsigned b = __float_as_uint(v);
    unsigned key = (b & 0x80000000u) ? ~b : (b | 0x80000000u);
    return ((u64)key << 32) | (unsigned)(~idx);
}

__device__ __forceinline__ u64 dup2(float f) {
    u64 r; asm("mov.b64 %0, {%1, %1};" : "=l"(r) : "f"(f)); return r;
}
__device__ __forceinline__ u64 pk2(float lo, float hi) {
    u64 r; asm("mov.b64 %0, {%1, %2};" : "=l"(r) : "f"(lo), "f"(hi)); return r;
}
__device__ __forceinline__ void upk2(u64 v, float& lo, float& hi) {
    asm("mov.b64 {%0, %1}, %2;" : "=f"(lo), "=f"(hi) : "l"(v));
}
__device__ __forceinline__ u64 fma2(u64 a, u64 b, u64 c) {
    u64 r; asm("fma.rn.f32x2 %0, %1, %2, %3;" : "=l"(r) : "l"(a), "l"(b), "l"(c)); return r;
}
__device__ __forceinline__ u64 mul2(u64 a, u64 b) {
    u64 r; asm("mul.rn.f32x2 %0, %1, %2;" : "=l"(r) : "l"(a), "l"(b)); return r;
}

// 9-term SH dot, SINGLE sequential chain per f32x2 half — exact R1 rounding
// order (verified rel_err 4.8e-8). DO NOT re-associate.
__device__ __forceinline__ u64 sig9p(const u64* C, ulonglong2 q0, ulonglong2 q1,
                                     ulonglong2 q2, ulonglong2 q3, u64 y8) {
    u64 acc = mul2(C[0], q0.x);
    acc = fma2(C[1], q0.y, acc);
    acc = fma2(C[2], q1.x, acc);
    acc = fma2(C[3], q1.y, acc);
    acc = fma2(C[4], q2.x, acc);
    acc = fma2(C[5], q2.y, acc);
    acc = fma2(C[6], q3.x, acc);
    acc = fma2(C[7], q3.y, acc);
    acc = fma2(C[8], y8, acc);
    return acc;
}
__device__ __forceinline__ u64 dot3p(u64 zx, u64 zy, u64 zz, u64 gx, u64 gy, u64 gz) {
    u64 d = mul2(zx, gx);
    d = fma2(zy, gy, d);
    return fma2(zz, gz, d);
}
// lower-g half checked first -> first-index tie-break preserved (strict >)
__device__ __forceinline__ void amax2(u64 s, int g0, float& bv, int& bi) {
    float lo, hi; upk2(s, lo, hi);
    if (lo > bv) { bv = lo; bi = g0; }
    if (hi > bv) { bv = hi; bi = g0 + 1; }
}
__device__ __forceinline__ void amaxm2(u64 s, u64 d, int g0, float& bv, int& bi) {
    float lo, hi, dl, dh; upk2(s, lo, hi); upk2(d, dl, dh);
    if (fabsf(dl) < 0.2f && lo > bv) { bv = lo; bi = g0; }
    if (fabsf(dh) < 0.2f && hi > bv) { bv = hi; bi = g0 + 1; }
}

__device__ __forceinline__ void shY(const float* __restrict__ grid, int g,
                                    float* Y, float* gv) {
    float gx = grid[3 * g + 0], gy = grid[3 * g + 1], gz = grid[3 * g + 2];
    gv[0] = gx; gv[1] = gy; gv[2] = gz;
    float n = sqrtf(gx * gx + gy * gy + gz * gz);
    float inv = 1.0f / fmaxf(n, 1e-12f);
    float x = gx * inv, y = gy * inv, z = gz * inv;
    float x2 = x * x, y2 = y * y, z2 = z * z;
    Y[0] = 2.5033429417967046f * (x * y * (x2 - y2));
    Y[1] = 1.7701307697799304f * (y * z * (3.0f * x2 - y2));
    Y[2] = 0.9461746957575601f * (x * y * (7.0f * z2 - 1.0f));
    Y[3] = 0.6690465435572892f * (y * z * (7.0f * z2 - 3.0f));
    Y[4] = 0.10578554691520431f * (35.0f * z2 * z2 - 30.0f * z2 + 3.0f);
    Y[5] = 0.6690465435572892f * (x * z * (7.0f * z2 - 3.0f));
    Y[6] = 0.47308734787878004f * ((x2 - y2) * (7.0f * z2 - 1.0f));
    Y[7] = 1.7701307697799304f * (x * z * (x2 - y2));
    Y[8] = 0.6258357354491761f * (x2 * x2 - 6.0f * x2 * y2 + y2 * y2);
}

// precompute SH table; also initializes per-row reduction scratch (fused).
__global__ void sh_precompute(const float* __restrict__ grid, int G, int P, int B) {
    int i = blockIdx.x * blockDim.x + threadIdx.x;
    if (i < B) { g_part1[i] = INIT_CAND; g_part2[i] = INIT_CAND; }
    if (i >= P) return;
    int g0 = 2 * i;
    int g1 = min(2 * i + 1, G - 1);
    float Ya[9], Yb[9], ga[3], gb[3];
    shY(grid, g0, Ya, ga);
    shY(grid, g1, Yb, gb);
    T1e t1; T2e t2;
#pragma unroll
    for (int q = 0; q < 9; q++) {
        u64 pr = pk2(Ya[q], Yb[q]);
        t1.v[q] = pr; t2.v[q] = pr;
    }
    t1.v[9] = 0;
    t2.v[9]  = pk2(ga[0], gb[0]);
    t2.v[10] = pk2(ga[1], gb[1]);
    t2.v[11] = pk2(ga[2], gb[2]);
    g_T1[i] = t1;
    g_T2[i] = t2;
}

__device__ __forceinline__ void stage16(const char* gsrc, uint32_t sdst, int bytes, int tid) {
    for (int i = tid * 16; i < bytes; i += BLOCK * 16)
        asm volatile("cp.async.cg.shared.global [%0], [%1], 16;"
                     :: "r"(sdst + (uint32_t)i), "l"(gsrc + i));
}
#define CPA_COMMIT() asm volatile("cp.async.commit_group;" ::: "memory")
#define CPA_WAIT1()  asm volatile("cp.async.wait_group 1;" ::: "memory")

// ---------------------------------------------------------------------------
// Pass 1: 4 rows per lane (128 rows/block) — halves per-FMA staging/LDS/ALU
// overhead. 2 blocks/SM (128-reg budget), SPLIT1=9 for wave fill.
// ---------------------------------------------------------------------------
__global__ __launch_bounds__(BLOCK, 2) void pass1_kernel(
    const float* __restrict__ f4, int B, int P, int Pq)
{
    __shared__ __align__(16) char sbuf[2][CHP * 80];
    __shared__ float s_pv[NW][RPB1];
    __shared__ int s_pidx[NW][RPB1];

    const int tid = threadIdx.x;
    const int lane = tid & 31;
    const int wid = tid >> 5;
    const int rowbase = blockIdx.x * RPB1;
    const int p0 = blockIdx.y * Pq;
    const int np = min(P - p0, Pq);
    const float NEG_INF = __int_as_float(0xff800000);

    const int rA = rowbase + lane;
    const int rB = rA + 32;
    const int rC = rA + 64;
    const int rD = rA + 96;

    u64 FA[9], FB[9], FC[9], FD[9];
#pragma unroll
    for (int i = 0; i < 9; i++) {
        FA[i] = dup2((rA < B) ? f4[rA * 9 + i] : 0.0f);
        FB[i] = dup2((rB < B) ? f4[rB * 9 + i] : 0.0f);
        FC[i] = dup2((rC < B) ? f4[rC * 9 + i] : 0.0f);
        FD[i] = dup2((rD < B) ? f4[rD * 9 + i] : 0.0f);
    }

    const int nch = (np + CHP - 1) / CHP;
    uint32_t sb[2];
    sb[0] = (uint32_t)__cvta_generic_to_shared(sbuf[0]);
    sb[1] = (uint32_t)__cvta_generic_to_shared(sbuf[1]);

    float bvA = NEG_INF, bvB = NEG_INF, bvC = NEG_INF, bvD = NEG_INF;
    int biA = 0, biB = 0, biC = 0, biD = 0;

    stage16((const char*)(g_T1 + p0), sb[0], min(CHP, np) * 80, tid);
    CPA_COMMIT();
    for (int c = 0; c < nch; c++) {
        int nxt = c + 1;
        if (nxt < nch)
            stage16((const char*)(g_T1 + p0 + nxt * CHP), sb[nxt & 1],
                    min(CHP, np - nxt * CHP) * 80, tid);
        CPA_COMMIT();
        CPA_WAIT1();
        __syncthreads();
        const char* buf = sbuf[c & 1];
        const int cnt = min(CHP, np - c * CHP);
        const int gb = (p0 + c * CHP) * 2;
        for (int k = wid; k < cnt; k += NW) {
            const ulonglong2* e = (const ulonglong2*)(buf + k * 80);
            ulonglong2 q0 = e[0], q1 = e[1], q2 = e[2], q3 = e[3], q4 = e[4];
            u64 aA = sig9p(FA, q0, q1, q2, q3, q4.x);
            u64 aB = sig9p(FB, q0, q1, q2, q3, q4.x);
            u64 aC = sig9p(FC, q0, q1, q2, q3, q4.x);
            u64 aD = sig9p(FD, q0, q1, q2, q3, q4.x);
            int g0 = gb + 2 * k;
            amax2(aA, g0, bvA, biA);
            amax2(aB, g0, bvB, biB);
            amax2(aC, g0, bvC, biC);
            amax2(aD, g0, bvD, biD);
        }
        __syncthreads();
    }

    s_pv[wid][lane]      = bvA; s_pidx[wid][lane]      = biA;
    s_pv[wid][lane + 32] = bvB; s_pidx[wid][lane + 32] = biB;
    s_pv[wid][lane + 64] = bvC; s_pidx[wid][lane + 64] = biC;
    s_pv[wid][lane + 96] = bvD; s_pidx[wid][lane + 96] = biD;
    __syncthreads();
    if (tid < RPB1) {
        int row = rowbase + tid;
        if (row < B) {
            float v = s_pv[0][tid]; int idx = s_pidx[0][tid];
#pragma unroll
            for (int w = 1; w < NW; w++) {
                float ov = s_pv[w][tid]; int oi = s_pidx[w][tid];
                if (ov > v || (ov == v && oi < idx)) { v = ov; idx = oi; }
            }
            atomicMax((unsigned long long*)&g_part1[row], packcand(v, idx));
        }
    }
}

// ---------------------------------------------------------------------------
// Pass 2: masked argmax; exact R8 config (2 rows/lane, 3 blocks/SM).
// ---------------------------------------------------------------------------
__global__ __launch_bounds__(BLOCK, 3) void pass2_kernel(
    const float* __restrict__ f4, const float* __restrict__ grid,
    int B, int P, int Pq)
{
    __shared__ __align__(16) char sbuf[2][CHP2 * 96];
    __shared__ float s_pv[NW][RPB2];
    __shared__ int s_pidx[NW][RPB2];

    const int tid = threadIdx.x;
    const int lane = tid & 31;
    const int wid = tid >> 5;
    const int rowbase = blockIdx.x * RPB2;
    const int p0 = blockIdx.y * Pq;
    const int np = min(P - p0, Pq);
    const float NEG_INF = __int_as_float(0xff800000);

    const int rA = rowbase + lane;
    const int rB = rA + 32;

    u64 FA[9], FB[9];
#pragma unroll
    for (int i = 0; i < 9; i++) {
        FA[i] = dup2((rA < B) ? f4[rA * 9 + i] : 0.0f);
        FB[i] = dup2((rB < B) ? f4[rB * 9 + i] : 0.0f);
    }
    int izA = (rA < B) ? ~(unsigned)g_part1[rA] : 0;
    int izB = (rB < B) ? ~(unsigned)g_part1[rB] : 0;
    const u64 ZAx = dup2(grid[3 * izA + 0]), ZAy = dup2(grid[3 * izA + 1]), ZAz = dup2(grid[3 * izA + 2]);
    const u64 ZBx = dup2(grid[3 * izB + 0]), ZBy = dup2(grid[3 * izB + 1]), ZBz = dup2(grid[3 * izB + 2]);

    const int nch = (np + CHP2 - 1) / CHP2;
    uint32_t sb[2];
    sb[0] = (uint32_t)__cvta_generic_to_shared(sbuf[0]);
    sb[1] = (uint32_t)__cvta_generic_to_shared(sbuf[1]);

    float bvA = NEG_INF, bvB = NEG_INF;
    int biA = 0, biB = 0;

    stage16((const char*)(g_T2 + p0), sb[0], min(CHP2, np) * 96, tid);
    CPA_COMMIT();
    for (int c = 0; c < nch; c++) {
        int nxt = c + 1;
        if (nxt < nch)
            stage16((const char*)(g_T2 + p0 + nxt * CHP2), sb[nxt & 1],
                    min(CHP2, np - nxt * CHP2) * 96, tid);
        CPA_COMMIT();
        CPA_WAIT1();
        __syncthreads();
        const char* buf = sbuf[c & 1];
        const int cnt = min(CHP2, np - c * CHP2);
        const int gb = (p0 + c * CHP2) * 2;
        for (int k = wid; k < cnt; k += NW) {
            const ulonglong2* e = (const ulonglong2*)(buf + k * 96);
            ulonglong2 q0 = e[0], q1 = e[1], q2 = e[2], q3 = e[3], q4 = e[4], q5 = e[5];
            u64 aA = sig9p(FA, q0, q1, q2, q3, q4.x);
            u64 aB = sig9p(FB, q0, q1, q2, q3, q4.x);
            u64 dA = dot3p(ZAx, ZAy, ZAz, q4.y, q5.x, q5.y);
            u64 dB = dot3p(ZBx, ZBy, ZBz, q4.y, q5.x, q5.y);
            int g0 = gb + 2 * k;
            amaxm2(aA, dA, g0, bvA, biA);
            amaxm2(aB, dB, g0, bvB, biB);
        }
        __syncthreads();
    }

    s_pv[wid][lane] = bvA;      s_pidx[wid][lane] = biA;
    s_pv[wid][lane + 32] = bvB; s_pidx[wid][lane + 32] = biB;
    __syncthreads();
    if (tid < RPB2) {
        int row = rowbase + tid;
        if (row < B) {
            float v = s_pv[0][tid]; int idx = s_pidx[0][tid];
#pragma unroll
            for (int w = 1; w < NW; w++) {
                float ov = s_pv[w][tid]; int oi = s_pidx[w][tid];
                if (ov > v || (ov == v && oi < idx)) { v = ov; idx = oi; }
            }
            atomicMax((unsigned long long*)&g_part2[row], packcand(v, idx));
        }
    }
}

// ---------------------------------------------------------------------------
// Epilogue: Gram-Schmidt + matrix->quaternion + boundary map.
// ---------------------------------------------------------------------------
__global__ void epilogue_kernel(const float* __restrict__ f0,
                                const float* __restrict__ grid,
                                float* __restrict__ out, int B)
{
    int row = blockIdx.x * blockDim.x + threadIdx.x;
    if (row >= B) return;
    int zi = ~(unsigned)g_part1[row];
    int xi = ~(unsigned)g_part2[row];
    float xr0 = grid[3 * xi + 0], xr1 = grid[3 * xi + 1], xr2 = grid[3 * xi + 2];
    float zr0 = grid[3 * zi + 0], zr1 = grid[3 * zi + 1], zr2 = grid[3 * zi + 2];
    float zn = sqrtf(zr0 * zr0 + zr1 * zr1 + zr2 * zr2);
    float zinv = 1.0f / fmaxf(zn, 1e-12f);
    float z0 = zr0 * zinv, z1 = zr1 * zinv, z2 = zr2 * zinv;
    float pr = xr0 * z0 + xr1 * z1 + xr2 * z2;
    float x0 = xr0 - pr * z0, x1 = xr1 - pr * z1, x2 = xr2 - pr * z2;
    float xn = sqrtf(x0 * x0 + x1 * x1 + x2 * x2);
    float xinv = 1.0f / fmaxf(xn, 1e-12f);
    x0 *= xinv; x1 *= xinv; x2 *= xinv;
    float y0 = z1 * x2 - z2 * x1;
    float y1 = z2 * x0 - z0 * x2;
    float y2 = z0 * x1 - z1 * x0;
    float m00 = x0, m01 = y0, m02 = z0;
    float m10 = x1, m11 = y1, m12 = z1;
    float m20 = x2, m21 = y2, m22 = z2;
    float qa0 = sqrtf(fmaxf(1.0f + m00 + m11 + m22, 0.0f));
    float qa1 = sqrtf(fmaxf(1.0f + m00 - m11 - m22, 0.0f));
    float qa2 = sqrtf(fmaxf(1.0f - m00 + m11 - m22, 0.0f));
    float qa3 = sqrtf(fmaxf(1.0f - m00 - m11 + m22, 0.0f));
    float c0[4] = {qa0 * qa0, m21 - m12, m02 - m20, m10 - m01};
    float c1[4] = {m21 - m12, qa1 * qa1, m10 + m01, m02 + m20};
    float c2[4] = {m02 - m20, m10 + m01, qa2 * qa2, m12 + m21};
    float c3[4] = {m10 - m01, m20 + m02, m21 + m12, qa3 * qa3};
    int best = 0; float bq = qa0;
    if (qa1 > bq) { bq = qa1; best = 1; }
    if (qa2 > bq) { bq = qa2; best = 2; }
    if (qa3 > bq) { bq = qa3; best = 3; }
    const float* cr = (best == 0) ? c0 : (best == 1) ? c1 : (best == 2) ? c2 : c3;
    float dn = 2.0f * fmaxf(bq, 0.1f);
    out[row * 4 + 0] = cr[0] / dn;
    out[row * 4 + 1] = cr[1] / dn;
    out[row * 4 + 2] = cr[2] / dn;
    out[row * 4 + 3] = cr[3] / dn;
    out[4 * B + row] = f0[row] * 57.29577951308232f;
}

extern "C" void kernel_launch(void* const* d_in, const int* in_sizes, int n_in,
                              void* d_out, int out_size) {
    const float* f0 = (const float*)d_in[0];
    const float* f4 = (const float*)d_in[2];
    const float* grid = (const float*)d_in[4];
    int B = in_sizes[0];
    int G = in_sizes[4] / 3;
    if (G > GMAX) G = GMAX;
    if (B > BMAX) B = BMAX;
    int P = (G + 1) / 2;
    int Pq1 = (P + SPLIT1 - 1) / SPLIT1;
    int Pq2 = (P + SPLIT2 - 1) / SPLIT2;

    int pre_n = (P > B) ? P : B;
    sh_precompute<<<(pre_n + 255) / 256, 256>>>(grid, G, P, B);

    dim3 gs1((B + RPB1 - 1) / RPB1, SPLIT1);
    dim3 gs2((B + RPB2 - 1) / RPB2, SPLIT2);
    pass1_kernel<<<gs1, BLOCK>>>(f4, B, P, Pq1);
    pass2_kernel<<<gs2, BLOCK>>>(f4, grid, B, P, Pq2);
    epilogue_kernel<<<(B + 255) / 256, 256>>>(f0, grid, (float*)d_out, B);
}

// round 16
// speedup vs baseline: 1.3012x; 1.0556x over previous
#include <cuda_runtime.h>
#include <math.h>
#include <stdint.h>

typedef unsigned long long u64;

#define GMAX 10240
#define PMAX (GMAX / 2)
#define BMAX 32768
#define NW 8
#define BLOCK 256
#define RPB1 128   // pass1: 4 rows per lane
#define RPB2 96    // pass2: 3 rows per lane
#define CHP 192    // pass1 chunk pairs (2*192*80 = 30.7KB)
#define CHP2 160   // pass2 chunk pairs (2*160*96 = 30.7KB)
#define SPLIT1 9
#define SPLIT2 5

// g-pair packed tables (no duplication):
// T1 (pass 1): v[0..8] = {Yi[g0], Yi[g1]} pairs, v[9] = pad      -> 80 B
// T2 (pass 2): v[0..8] = Y pairs, v[9]=gx pair, v[10]=gy, v[11]=gz -> 96 B
struct __align__(16) T1e { u64 v[10]; };
struct __align__(16) T2e { u64 v[12]; };
__device__ T1e g_T1[PMAX];
__device__ T2e g_T2[PMAX];

// cross-block reduction scratch: packed (sortable_value<<32 | ~index)
__device__ u64 g_part1[BMAX];
__device__ u64 g_part2[BMAX];

// packed(-inf, idx=0): key(-inf)=0x007FFFFF, ~0 = 0xFFFFFFFF
#define INIT_CAND 0x007FFFFFFFFFFFFFULL

__device__ __forceinline__ u64 packcand(float v, int idx) {
    unsigned b = __float_as_uint(v);
    unsigned key = (b & 0x80000000u) ? ~b : (b | 0x80000000u);
    return ((u64)key << 32) | (unsigned)(~idx);
}

__device__ __forceinline__ u64 dup2(float f) {
    u64 r; asm("mov.b64 %0, {%1, %1};" : "=l"(r) : "f"(f)); return r;
}
__device__ __forceinline__ u64 pk2(float lo, float hi) {
    u64 r; asm("mov.b64 %0, {%1, %2};" : "=l"(r) : "f"(lo), "f"(hi)); return r;
}
__device__ __forceinline__ void upk2(u64 v, float& lo, float& hi) {
    asm("mov.b64 {%0, %1}, %2;" : "=f"(lo), "=f"(hi) : "l"(v));
}
__device__ __forceinline__ u64 fma2(u64 a, u64 b, u64 c) {
    u64 r; asm("fma.rn.f32x2 %0, %1, %2, %3;" : "=l"(r) : "l"(a), "l"(b), "l"(c)); return r;
}
__device__ __forceinline__ u64 mul2(u64 a, u64 b) {
    u64 r; asm("mul.rn.f32x2 %0, %1, %2;" : "=l"(r) : "l"(a), "l"(b)); return r;
}

// 9-term SH dot, SINGLE sequential chain per f32x2 half — exact R1 rounding
// order (verified rel_err 4.8e-8). DO NOT re-associate.
__device__ __forceinline__ u64 sig9p(const u64* C, ulonglong2 q0, ulonglong2 q1,
                                     ulonglong2 q2, ulonglong2 q3, u64 y8) {
    u64 acc = mul2(C[0], q0.x);
    acc = fma2(C[1], q0.y, acc);
    acc = fma2(C[2], q1.x, acc);
    acc = fma2(C[3], q1.y, acc);
    acc = fma2(C[4], q2.x, acc);
    acc = fma2(C[5], q2.y, acc);
    acc = fma2(C[6], q3.x, acc);
    acc = fma2(C[7], q3.y, acc);
    acc = fma2(C[8], y8, acc);
    return acc;
}
__device__ __forceinline__ u64 dot3p(u64 zx, u64 zy, u64 zz, u64 gx, u64 gy, u64 gz) {
    u64 d = mul2(zx, gx);
    d = fma2(zy, gy, d);
    return fma2(zz, gz, d);
}
// lower-g half checked first -> first-index tie-break preserved (strict >)
__device__ __forceinline__ void amax2(u64 s, int g0, float& bv, int& bi) {
    float lo, hi; upk2(s, lo, hi);
    if (lo > bv) { bv = lo; bi = g0; }
    if (hi > bv) { bv = hi; bi = g0 + 1; }
}
__device__ __forceinline__ void amaxm2(u64 s, u64 d, int g0, float& bv, int& bi) {
    float lo, hi, dl, dh; upk2(s, lo, hi); upk2(d, dl, dh);
    if (fabsf(dl) < 0.2f && lo > bv) { bv = lo; bi = g0; }
    if (fabsf(dh) < 0.2f && hi > bv) { bv = hi; bi = g0 + 1; }
}

__device__ __forceinline__ void shY(const float* __restrict__ grid, int g,
                                    float* Y, float* gv) {
    float gx = grid[3 * g + 0], gy = grid[3 * g + 1], gz = grid[3 * g + 2];
    gv[0] = gx; gv[1] = gy; gv[2] = gz;
    float n = sqrtf(gx * gx + gy * gy + gz * gz);
    float inv = 1.0f / fmaxf(n, 1e-12f);
    float x = gx * inv, y = gy * inv, z = gz * inv;
    float x2 = x * x, y2 = y * y, z2 = z * z;
    Y[0] = 2.5033429417967046f * (x * y * (x2 - y2));
    Y[1] = 1.7701307697799304f * (y * z * (3.0f * x2 - y2));
    Y[2] = 0.9461746957575601f * (x * y * (7.0f * z2 - 1.0f));
    Y[3] = 0.6690465435572892f * (y * z * (7.0f * z2 - 3.0f));
    Y[4] = 0.10578554691520431f * (35.0f * z2 * z2 - 30.0f * z2 + 3.0f);
    Y[5] = 0.6690465435572892f * (x * z * (7.0f * z2 - 3.0f));
    Y[6] = 0.47308734787878004f * ((x2 - y2) * (7.0f * z2 - 1.0f));
    Y[7] = 1.7701307697799304f * (x * z * (x2 - y2));
    Y[8] = 0.6258357354491761f * (x2 * x2 - 6.0f * x2 * y2 + y2 * y2);
}

// precompute SH table; also initializes per-row reduction scratch (fused).
__global__ void sh_precompute(const float* __restrict__ grid, int G, int P, int B) {
    int i = blockIdx.x * blockDim.x + threadIdx.x;
    if (i < B) { g_part1[i] = INIT_CAND; g_part2[i] = INIT_CAND; }
    if (i >= P) return;
    int g0 = 2 * i;
    int g1 = min(2 * i + 1, G - 1);
    float Ya[9], Yb[9], ga[3], gb[3];
    shY(grid, g0, Ya, ga);
    shY(grid, g1, Yb, gb);
    T1e t1; T2e t2;
#pragma unroll
    for (int q = 0; q < 9; q++) {
        u64 pr = pk2(Ya[q], Yb[q]);
        t1.v[q] = pr; t2.v[q] = pr;
    }
    t1.v[9] = 0;
    t2.v[9]  = pk2(ga[0], gb[0]);
    t2.v[10] = pk2(ga[1], gb[1]);
    t2.v[11] = pk2(ga[2], gb[2]);
    g_T1[i] = t1;
    g_T2[i] = t2;
}

__device__ __forceinline__ void stage16(const char* gsrc, uint32_t sdst, int bytes, int tid) {
    for (int i = tid * 16; i < bytes; i += BLOCK * 16)
        asm volatile("cp.async.cg.shared.global [%0], [%1], 16;"
                     :: "r"(sdst + (uint32_t)i), "l"(gsrc + i));
}
#define CPA_COMMIT() asm volatile("cp.async.commit_group;" ::: "memory")
#define CPA_WAIT1()  asm volatile("cp.async.wait_group 1;" ::: "memory")

// ---------------------------------------------------------------------------
// Pass 1: 4 rows per lane (128 rows/block); 2 blocks/SM; SPLIT1=9.
// ---------------------------------------------------------------------------
__global__ __launch_bounds__(BLOCK, 2) void pass1_kernel(
    const float* __restrict__ f4, int B, int P, int Pq)
{
    __shared__ __align__(16) char sbuf[2][CHP * 80];
    __shared__ float s_pv[NW][RPB1];
    __shared__ int s_pidx[NW][RPB1];

    const int tid = threadIdx.x;
    const int lane = tid & 31;
    const int wid = tid >> 5;
    const int rowbase = blockIdx.x * RPB1;
    const int p0 = blockIdx.y * Pq;
    const int np = min(P - p0, Pq);
    const float NEG_INF = __int_as_float(0xff800000);

    const int rA = rowbase + lane;
    const int rB = rA + 32;
    const int rC = rA + 64;
    const int rD = rA + 96;

    u64 FA[9], FB[9], FC[9], FD[9];
#pragma unroll
    for (int i = 0; i < 9; i++) {
        FA[i] = dup2((rA < B) ? f4[rA * 9 + i] : 0.0f);
        FB[i] = dup2((rB < B) ? f4[rB * 9 + i] : 0.0f);
        FC[i] = dup2((rC < B) ? f4[rC * 9 + i] : 0.0f);
        FD[i] = dup2((rD < B) ? f4[rD * 9 + i] : 0.0f);
    }

    const int nch = (np + CHP - 1) / CHP;
    uint32_t sb[2];
    sb[0] = (uint32_t)__cvta_generic_to_shared(sbuf[0]);
    sb[1] = (uint32_t)__cvta_generic_to_shared(sbuf[1]);

    float bvA = NEG_INF, bvB = NEG_INF, bvC = NEG_INF, bvD = NEG_INF;
    int biA = 0, biB = 0, biC = 0, biD = 0;

    stage16((const char*)(g_T1 + p0), sb[0], min(CHP, np) * 80, tid);
    CPA_COMMIT();
    for (int c = 0; c < nch; c++) {
        int nxt = c + 1;
        if (nxt < nch)
            stage16((const char*)(g_T1 + p0 + nxt * CHP), sb[nxt & 1],
                    min(CHP, np - nxt * CHP) * 80, tid);
        CPA_COMMIT();
        CPA_WAIT1();
        __syncthreads();
        const char* buf = sbuf[c & 1];
        const int cnt = min(CHP, np - c * CHP);
        const int gb = (p0 + c * CHP) * 2;
        for (int k = wid; k < cnt; k += NW) {
            const ulonglong2* e = (const ulonglong2*)(buf + k * 80);
            ulonglong2 q0 = e[0], q1 = e[1], q2 = e[2], q3 = e[3], q4 = e[4];
            u64 aA = sig9p(FA, q0, q1, q2, q3, q4.x);
            u64 aB = sig9p(FB, q0, q1, q2, q3, q4.x);
            u64 aC = sig9p(FC, q0, q1, q2, q3, q4.x);
            u64 aD = sig9p(FD, q0, q1, q2, q3, q4.x);
            int g0 = gb + 2 * k;
            amax2(aA, g0, bvA, biA);
            amax2(aB, g0, bvB, biB);
            amax2(aC, g0, bvC, biC);
            amax2(aD, g0, bvD, biD);
        }
        __syncthreads();
    }

    s_pv[wid][lane]      = bvA; s_pidx[wid][lane]      = biA;
    s_pv[wid][lane + 32] = bvB; s_pidx[wid][lane + 32] = biB;
    s_pv[wid][lane + 64] = bvC; s_pidx[wid][lane + 64] = biC;
    s_pv[wid][lane + 96] = bvD; s_pidx[wid][lane + 96] = biD;
    __syncthreads();
    if (tid < RPB1) {
        int row = rowbase + tid;
        if (row < B) {
            float v = s_pv[0][tid]; int idx = s_pidx[0][tid];
#pragma unroll
            for (int w = 1; w < NW; w++) {
                float ov = s_pv[w][tid]; int oi = s_pidx[w][tid];
                if (ov > v || (ov == v && oi < idx)) { v = ov; idx = oi; }
            }
            atomicMax((unsigned long long*)&g_part1[row], packcand(v, idx));
        }
    }
}

// ---------------------------------------------------------------------------
// Pass 2: masked argmax, 3 rows per lane (96 rows/block); 2 blocks/SM.
// ---------------------------------------------------------------------------
__global__ __launch_bounds__(BLOCK, 2) void pass2_kernel(
    const float* __restrict__ f4, const float* __restrict__ grid,
    int B, int P, int Pq)
{
    __shared__ __align__(16) char sbuf[2][CHP2 * 96];
    __shared__ float s_pv[NW][RPB2];
    __shared__ int s_pidx[NW][RPB2];

    const int tid = threadIdx.x;
    const int lane = tid & 31;
    const int wid = tid >> 5;
    const int rowbase = blockIdx.x * RPB2;
    const int p0 = blockIdx.y * Pq;
    const int np = min(P - p0, Pq);
    const float NEG_INF = __int_as_float(0xff800000);

    const int rA = rowbase + lane;
    const int rB = rA + 32;
    const int rC = rA + 64;

    u64 FA[9], FB[9], FC[9];
#pragma unroll
    for (int i = 0; i < 9; i++) {
        FA[i] = dup2((rA < B) ? f4[rA * 9 + i] : 0.0f);
        FB[i] = dup2((rB < B) ? f4[rB * 9 + i] : 0.0f);
        FC[i] = dup2((rC < B) ? f4[rC * 9 + i] : 0.0f);
    }
    int izA = (rA < B) ? ~(unsigned)g_part1[rA] : 0;
    int izB = (rB < B) ? ~(unsigned)g_part1[rB] : 0;
    int izC = (rC < B) ? ~(unsigned)g_part1[rC] : 0;
    const u64 ZAx = dup2(grid[3 * izA + 0]), ZAy = dup2(grid[3 * izA + 1]), ZAz = dup2(grid[3 * izA + 2]);
    const u64 ZBx = dup2(grid[3 * izB + 0]), ZBy = dup2(grid[3 * izB + 1]), ZBz = dup2(grid[3 * izB + 2]);
    const u64 ZCx = dup2(grid[3 * izC + 0]), ZCy = dup2(grid[3 * izC + 1]), ZCz = dup2(grid[3 * izC + 2]);

    const int nch = (np + CHP2 - 1) / CHP2;
    uint32_t sb[2];
    sb[0] = (uint32_t)__cvta_generic_to_shared(sbuf[0]);
    sb[1] = (uint32_t)__cvta_generic_to_shared(sbuf[1]);

    float bvA = NEG_INF, bvB = NEG_INF, bvC = NEG_INF;
    int biA = 0, biB = 0, biC = 0;

    stage16((const char*)(g_T2 + p0), sb[0], min(CHP2, np) * 96, tid);
    CPA_COMMIT();
    for (int c = 0; c < nch; c++) {
        int nxt = c + 1;
        if (nxt < nch)
            stage16((const char*)(g_T2 + p0 + nxt * CHP2), sb[nxt & 1],
                    min(CHP2, np - nxt * CHP2) * 96, tid);
        CPA_COMMIT();
        CPA_WAIT1();
        __syncthreads();
        const char* buf = sbuf[c & 1];
        const int cnt = min(CHP2, np - c * CHP2);
        const int gb = (p0 + c * CHP2) * 2;
        for (int k = wid; k < cnt; k += NW) {
            const ulonglong2* e = (const ulonglong2*)(buf + k * 96);
            ulonglong2 q0 = e[0], q1 = e[1], q2 = e[2], q3 = e[3], q4 = e[4], q5 = e[5];
            u64 aA = sig9p(FA, q0, q1, q2, q3, q4.x);
            u64 aB = sig9p(FB, q0, q1, q2, q3, q4.x);
            u64 aC = sig9p(FC, q0, q1, q2, q3, q4.x);
            u64 dA = dot3p(ZAx, ZAy, ZAz, q4.y, q5.x, q5.y);
            u64 dB = dot3p(ZBx, ZBy, ZBz, q4.y, q5.x, q5.y);
            u64 dC = dot3p(ZCx, ZCy, ZCz, q4.y, q5.x, q5.y);
            int g0 = gb + 2 * k;
            amaxm2(aA, dA, g0, bvA, biA);
            amaxm2(aB, dB, g0, bvB, biB);
            amaxm2(aC, dC, g0, bvC, biC);
        }
        __syncthreads();
    }

    s_pv[wid][lane]      = bvA; s_pidx[wid][lane]      = biA;
    s_pv[wid][lane + 32] = bvB; s_pidx[wid][lane + 32] = biB;
    s_pv[wid][lane + 64] = bvC; s_pidx[wid][lane + 64] = biC;
    __syncthreads();
    if (tid < RPB2) {
        int row = rowbase + tid;
        if (row < B) {
            float v = s_pv[0][tid]; int idx = s_pidx[0][tid];
#pragma unroll
            for (int w = 1; w < NW; w++) {
                float ov = s_pv[w][tid]; int oi = s_pidx[w][tid];
                if (ov > v || (ov == v && oi < idx)) { v = ov; idx = oi; }
            }
            atomicMax((unsigned long long*)&g_part2[row], packcand(v, idx));
        }
    }
}

// ---------------------------------------------------------------------------
// Epilogue: Gram-Schmidt + matrix->quaternion + boundary map.
// ---------------------------------------------------------------------------
__global__ void epilogue_kernel(const float* __restrict__ f0,
                                const float* __restrict__ grid,
                                float* __restrict__ out, int B)
{
    int row = blockIdx.x * blockDim.x + threadIdx.x;
    if (row >= B) return;
    int zi = ~(unsigned)g_part1[row];
    int xi = ~(unsigned)g_part2[row];
    float xr0 = grid[3 * xi + 0], xr1 = grid[3 * xi + 1], xr2 = grid[3 * xi + 2];
    float zr0 = grid[3 * zi + 0], zr1 = grid[3 * zi + 1], zr2 = grid[3 * zi + 2];
    float zn = sqrtf(zr0 * zr0 + zr1 * zr1 + zr2 * zr2);
    float zinv = 1.0f / fmaxf(zn, 1e-12f);
    float z0 = zr0 * zinv, z1 = zr1 * zinv, z2 = zr2 * zinv;
    float pr = xr0 * z0 + xr1 * z1 + xr2 * z2;
    float x0 = xr0 - pr * z0, x1 = xr1 - pr * z1, x2 = xr2 - pr * z2;
    float xn = sqrtf(x0 * x0 + x1 * x1 + x2 * x2);
    float xinv = 1.0f / fmaxf(xn, 1e-12f);
    x0 *= xinv; x1 *= xinv; x2 *= xinv;
    float y0 = z1 * x2 - z2 * x1;
    float y1 = z2 * x0 - z0 * x2;
    float y2 = z0 * x1 - z1 * x0;
    float m00 = x0, m01 = y0, m02 = z0;
    float m10 = x1, m11 = y1, m12 = z1;
    float m20 = x2, m21 = y2, m22 = z2;
    float qa0 = sqrtf(fmaxf(1.0f + m00 + m11 + m22, 0.0f));
    float qa1 = sqrtf(fmaxf(1.0f + m00 - m11 - m22, 0.0f));
    float qa2 = sqrtf(fmaxf(1.0f - m00 + m11 - m22, 0.0f));
    float qa3 = sqrtf(fmaxf(1.0f - m00 - m11 + m22, 0.0f));
    float c0[4] = {qa0 * qa0, m21 - m12, m02 - m20, m10 - m01};
    float c1[4] = {m21 - m12, qa1 * qa1, m10 + m01, m02 + m20};
    float c2[4] = {m02 - m20, m10 + m01, qa2 * qa2, m12 + m21};
    float c3[4] = {m10 - m01, m20 + m02, m21 + m12, qa3 * qa3};
    int best = 0; float bq = qa0;
    if (qa1 > bq) { bq = qa1; best = 1; }
    if (qa2 > bq) { bq = qa2; best = 2; }
    if (qa3 > bq) { bq = qa3; best = 3; }
    const float* cr = (best == 0) ? c0 : (best == 1) ? c1 : (best == 2) ? c2 : c3;
    float dn = 2.0f * fmaxf(bq, 0.1f);
    out[row * 4 + 0] = cr[0] / dn;
    out[row * 4 + 1] = cr[1] / dn;
    out[row * 4 + 2] = cr[2] / dn;
    out[row * 4 + 3] = cr[3] / dn;
    out[4 * B + row] = f0[row] * 57.29577951308232f;
}

extern "C" void kernel_launch(void* const* d_in, const int* in_sizes, int n_in,
                              void* d_out, int out_size) {
    const float* f0 = (const float*)d_in[0];
    const float* f4 = (const float*)d_in[2];
    const float* grid = (const float*)d_in[4];
    int B = in_sizes[0];
    int G = in_sizes[4] / 3;
    if (G > GMAX) G = GMAX;
    if (B > BMAX) B = BMAX;
    int P = (G + 1) / 2;
    int Pq1 = (P + SPLIT1 - 1) / SPLIT1;
    int Pq2 = (P + SPLIT2 - 1) / SPLIT2;

    int pre_n = (P > B) ? P : B;
    sh_precompute<<<(pre_n + 255) / 256, 256>>>(grid, G, P, B);

    dim3 gs1((B + RPB1 - 1) / RPB1, SPLIT1);
    dim3 gs2((B + RPB2 - 1) / RPB2, SPLIT2);
    pass1_kernel<<<gs1, BLOCK>>>(f4, B, P, Pq1);
    pass2_kernel<<<gs2, BLOCK>>>(f4, grid, B, P, Pq2);
    epilogue_kernel<<<(B + 255) / 256, 256>>>(f0, grid, (float*)d_out, B);
}